// round 15
// baseline (speedup 1.0000x reference)
#include <cuda_runtime.h>
#include <cuda_bf16.h>
#include <math.h>

// ---------------------------------------------------------------------------
// Problem constants
// ---------------------------------------------------------------------------
#define Bsz   32
#define Tlen  16
#define Slen  400
#define Hd    300
#define Ed    300
#define Ld    3
#define Vocab 50000
#define OOV   20
#define ROWS  (Bsz*Tlen)      // 512
#define VO    (Vocab+OOV)     // 50020
#define CATW  900             // [contexts(300) | hiddens(300) | x(300)]

// Persistent GRU config
#define NBLK  100
#define NTHR  864
#define NJ    3
#define SB    308

// GRU smem layout (floats)
#define SW_FLOATS   16200
#define SX_OFF      16200
#define SH_OFF      (SX_OFF + Bsz*SB)
#define SACC_OFF    (SH_OFF + Bsz*SB)
#define SBIAS_OFF   (SACC_OFF + 18*96)
#define SMEM_FLOATS (SBIAS_OFF + 54)
#define SMEM_BYTES  (SMEM_FLOATS*4)

#define FMA2(acc, x, y) asm("fma.rn.f32x2 %0, %1, %2, %0;" : "+l"(acc) : "l"(x), "l"(y))

// MMA out-GEMM config
#define SA     40             // smem tile stride in bf16 (LDSM conflict-free: r*20 mod 32 covers all bank-quads)

#define MMA_BF16(c, a, b) \
    asm volatile("mma.sync.aligned.m16n8k16.row.col.f32.bf16.bf16.f32 " \
        "{%0,%1,%2,%3}, {%4,%5,%6,%7}, {%8,%9}, {%0,%1,%2,%3};" \
        : "+f"((c)[0]), "+f"((c)[1]), "+f"((c)[2]), "+f"((c)[3]) \
        : "r"((a)[0]), "r"((a)[1]), "r"((a)[2]), "r"((a)[3]), \
          "r"((b)[0]), "r"((b)[1]))

#define LDSM_X4(r, a) \
    asm volatile("ldmatrix.sync.aligned.m8n8.x4.shared.b16 {%0,%1,%2,%3}, [%4];" \
        : "=r"((r)[0]), "=r"((r)[1]), "=r"((r)[2]), "=r"((r)[3]) : "r"(a))
#define LDSM_X2(r, a) \
    asm volatile("ldmatrix.sync.aligned.m8n8.x2.shared.b16 {%0,%1}, [%2];" \
        : "=r"((r)[0]), "=r"((r)[1]) : "r"(a))

// attn v2 smem layout (floats): q[8][304] | probs[8][400] | src chunk [32][308]
#define AQ_OFF    0
#define ASC_OFF   2432
#define ASRC_OFF  (2432 + 3200)            // 5632
#define ATT_FLOATS (5632 + 32*308)         // 15488
#define ATT_BYTES  (ATT_FLOATS*4)          // 61952

// ---------------------------------------------------------------------------
// Scratch
// ---------------------------------------------------------------------------
__device__ float g_cat[ROWS*CATW];
__device__ float g_hall[Ld][Tlen+1][Bsz][Hd];
__device__ float g_q[ROWS*Hd];
__device__ float g_feat[ROWS*Hd];
__device__ float g_logits[(size_t)ROWS*Vocab];     // exp(logit) after out-GEMM
__device__ float g_rowsum[ROWS];
__device__ float g_pgen[ROWS*2];
__device__ float g_attn_fallback[ROWS*Slen];
__device__ int   g_mask_u8;

__device__ unsigned g_bar_cnt = 0;
__device__ unsigned g_bar_gen = 0;

// ---------------------------------------------------------------------------
__device__ __forceinline__ unsigned smem_u32(const void* p) {
    unsigned a;
    asm("{ .reg .u64 t; cvta.to.shared.u64 t, %1; cvt.u32.u64 %0, t; }" : "=r"(a) : "l"(p));
    return a;
}

__global__ void detect_mask_kernel(const unsigned char* __restrict__ m) {
    g_mask_u8 = (m[1] | m[2] | m[3]) ? 1 : 0;
}

__global__ void init_hall_kernel(const float* __restrict__ h0) {
    int i = blockIdx.x*blockDim.x + threadIdx.x;
    if (i < Ld*Bsz*Hd) {
        int l = i / (Bsz*Hd), r = i - l*(Bsz*Hd);
        (&g_hall[l][0][0][0])[r] = h0[i];
    }
    if (i < ROWS) g_rowsum[i] = 0.f;
}

__global__ void embed_kernel(const int* __restrict__ tokens,
                             const float* __restrict__ embed) {
    int i = blockIdx.x*blockDim.x + threadIdx.x;
    if (i < ROWS*Ed) {
        int row = i / Ed, e = i - row*Ed;
        g_cat[row*CATW + 600 + e] = embed[(size_t)tokens[row]*Ed + e];
    }
}

// ---------------------------------------------------------------------------
// Grid barrier
// ---------------------------------------------------------------------------
__device__ __forceinline__ void grid_barrier() {
    __threadfence();
    __syncthreads();
    if (threadIdx.x == 0) {
        unsigned gen = *(volatile unsigned*)&g_bar_gen;
        if (atomicAdd(&g_bar_cnt, 1u) == NBLK - 1u) {
            atomicExch(&g_bar_cnt, 0u);
            __threadfence();
            atomicAdd(&g_bar_gen, 1u);
        } else {
            while (*(volatile unsigned*)&g_bar_gen == gen) __nanosleep(32);
        }
        __threadfence();
    }
    __syncthreads();
}

// ---------------------------------------------------------------------------
// GRU activation prefetch (registers)
// ---------------------------------------------------------------------------
__device__ __forceinline__ void gru_prefetch(int l, int t, int tid,
                                             float4* px, float4* ph) {
    const float* xsrc; size_t xstr;
    if (l == 0) { xsrc = g_cat + t*CATW + 600; xstr = Tlen*CATW; }
    else        { xsrc = &g_hall[l-1][t+1][0][0]; xstr = Hd; }
    const float* hsrc = &g_hall[l][t][0][0];
    #pragma unroll
    for (int it = 0; it < 3; it++) {
        int i = tid + it*NTHR;
        if (i < Bsz*75) {
            int b = i / 75, q4 = (i - b*75)*4;
            px[it] = *(const float4*)(xsrc + (size_t)b*xstr + q4);
            ph[it] = *(const float4*)(hsrc + b*Hd + q4);
        }
    }
}

// ---------------------------------------------------------------------------
// Persistent GRU v5.1 (unchanged)
// ---------------------------------------------------------------------------
extern __shared__ float s_dyn[];

__global__ void __launch_bounds__(NTHR) gru_persistent_kernel(
        const float* __restrict__ W_ih, const float* __restrict__ W_hh,
        const float* __restrict__ b_ih, const float* __restrict__ b_hh) {
    float* sw   = s_dyn;
    float* sx   = s_dyn + SX_OFF;
    float* sh   = s_dyn + SH_OFF;
    float* sacc = s_dyn + SACC_OFF;
    float* sb   = s_dyn + SBIAS_OFF;

    const int tid  = threadIdx.x;
    const int j0   = blockIdx.x * NJ;
    const int lane = tid & 31, w = tid >> 5;
    const int p = w / 3, q = w - 3*p;
    const int tA = 2*p, tB = tA + 1;
    const int kbeg = q * 100;

    for (int idx = tid; idx < SW_FLOATS; idx += NTHR) {
        int l = idx / 5400, r = idx - l*5400;
        int task = r / 300, k = r - task*300;
        int m = task / 9, t2 = task - m*9;
        int g = t2 / 3, jl = t2 - g*3;
        int row = g*300 + j0 + jl;
        const float* src = (m == 0) ? W_ih : W_hh;
        sw[idx] = src[(size_t)l*270000 + (size_t)row*300 + k];
    }
    if (tid < 54) {
        int l = tid / 18, r = tid % 18;
        int m = r / 9, r2 = r % 9;
        int g = r2 / 3, jl = r2 % 3;
        const float* src = m ? b_hh : b_ih;
        sb[tid] = src[l*900 + g*300 + j0 + jl];
    }

    float4 px[3], ph[3];
    gru_prefetch(0, 0, tid, px, ph);

    for (int wf = 0; wf < Tlen + Ld - 1; wf++) {
        int lmin = wf - (Tlen-1); if (lmin < 0) lmin = 0;
        int lmax = (wf < Ld-1) ? wf : Ld-1;
        for (int l = lmin; l <= lmax; l++) {
            int t = wf - l;

            if (l != lmin) __syncthreads();

            #pragma unroll
            for (int it = 0; it < 3; it++) {
                int i = tid + it*NTHR;
                if (i < Bsz*75) {
                    int b = i / 75, q4 = (i - b*75)*4;
                    *(float4*)&sx[b*SB + q4] = px[it];
                    *(float4*)&sh[b*SB + q4] = ph[it];
                }
            }
            __syncthreads();

            if (l < lmax) gru_prefetch(l+1, t-1, tid, px, ph);

            {
                const float* wA = sw + (l*18 + tA)*300;
                const float* wB = sw + (l*18 + tB)*300;
                const float* aA = ((tA < 9) ? sx : sh) + lane*SB;
                const float* aB = ((tB < 9) ? sx : sh) + lane*SB;
                unsigned long long accA0 = 0ull, accA1 = 0ull;
                unsigned long long accB0 = 0ull, accB1 = 0ull;
                if (p != 4) {
                    #pragma unroll 4
                    for (int kk = 0; kk < 96; kk += 8) {
                        int k = kbeg + kk;
                        ulonglong2 wa0 = *(const ulonglong2*)(wA + k);
                        ulonglong2 wa1 = *(const ulonglong2*)(wA + k + 4);
                        ulonglong2 wb0 = *(const ulonglong2*)(wB + k);
                        ulonglong2 wb1 = *(const ulonglong2*)(wB + k + 4);
                        ulonglong2 x01 = *(const ulonglong2*)(aA + k);
                        ulonglong2 x23 = *(const ulonglong2*)(aA + k + 4);
                        FMA2(accA0, wa0.x, x01.x); FMA2(accA1, wa0.y, x01.y);
                        FMA2(accB0, wb0.x, x01.x); FMA2(accB1, wb0.y, x01.y);
                        FMA2(accA0, wa1.x, x23.x); FMA2(accA1, wa1.y, x23.y);
                        FMA2(accB0, wb1.x, x23.x); FMA2(accB1, wb1.y, x23.y);
                    }
                    {
                        int k = kbeg + 96;
                        ulonglong2 wa = *(const ulonglong2*)(wA + k);
                        ulonglong2 wb = *(const ulonglong2*)(wB + k);
                        ulonglong2 x01 = *(const ulonglong2*)(aA + k);
                        FMA2(accA0, wa.x, x01.x); FMA2(accA1, wa.y, x01.y);
                        FMA2(accB0, wb.x, x01.x); FMA2(accB1, wb.y, x01.y);
                    }
                } else {
                    #pragma unroll 4
                    for (int kk = 0; kk < 96; kk += 8) {
                        int k = kbeg + kk;
                        ulonglong2 wa0 = *(const ulonglong2*)(wA + k);
                        ulonglong2 wa1 = *(const ulonglong2*)(wA + k + 4);
                        ulonglong2 wb0 = *(const ulonglong2*)(wB + k);
                        ulonglong2 wb1 = *(const ulonglong2*)(wB + k + 4);
                        ulonglong2 x01 = *(const ulonglong2*)(aA + k);
                        ulonglong2 x23 = *(const ulonglong2*)(aA + k + 4);
                        ulonglong2 y01 = *(const ulonglong2*)(aB + k);
                        ulonglong2 y23 = *(const ulonglong2*)(aB + k + 4);
                        FMA2(accA0, wa0.x, x01.x); FMA2(accA1, wa0.y, x01.y);
                        FMA2(accB0, wb0.x, y01.x); FMA2(accB1, wb0.y, y01.y);
                        FMA2(accA0, wa1.x, x23.x); FMA2(accA1, wa1.y, x23.y);
                        FMA2(accB0, wb1.x, y23.x); FMA2(accB1, wb1.y, y23.y);
                    }
                    {
                        int k = kbeg + 96;
                        ulonglong2 wa = *(const ulonglong2*)(wA + k);
                        ulonglong2 wb = *(const ulonglong2*)(wB + k);
                        ulonglong2 x01 = *(const ulonglong2*)(aA + k);
                        ulonglong2 y01 = *(const ulonglong2*)(aB + k);
                        FMA2(accA0, wa.x, x01.x); FMA2(accA1, wa.y, x01.y);
                        FMA2(accB0, wb.x, y01.x); FMA2(accB1, wb.y, y01.y);
                    }
                }
                float a0,a1,a2,a3;
                asm("mov.b64 {%0,%1}, %2;" : "=f"(a0), "=f"(a1) : "l"(accA0));
                asm("mov.b64 {%0,%1}, %2;" : "=f"(a2), "=f"(a3) : "l"(accA1));
                sacc[tA*96 + q*32 + lane] = (a0+a1) + (a2+a3);
                asm("mov.b64 {%0,%1}, %2;" : "=f"(a0), "=f"(a1) : "l"(accB0));
                asm("mov.b64 {%0,%1}, %2;" : "=f"(a2), "=f"(a3) : "l"(accB1));
                sacc[tB*96 + q*32 + lane] = (a0+a1) + (a2+a3);
            }
            __syncthreads();

            if (tid < 96) {
                int b = tid & 31, jl = tid >> 5;
                int j = j0 + jl;
                #define SAC(tk) (sacc[(tk)*96+b] + sacc[(tk)*96+32+b] + sacc[(tk)*96+64+b])
                float i_r = SAC( 0+jl) + sb[l*18 +      jl];
                float i_z = SAC( 3+jl) + sb[l*18 +  3 + jl];
                float i_n = SAC( 6+jl) + sb[l*18 +  6 + jl];
                float h_r = SAC( 9+jl) + sb[l*18 +  9 + jl];
                float h_z = SAC(12+jl) + sb[l*18 + 12 + jl];
                float h_n = SAC(15+jl) + sb[l*18 + 15 + jl];
                #undef SAC
                float r = 1.f/(1.f + __expf(-(i_r + h_r)));
                float z = 1.f/(1.f + __expf(-(i_z + h_z)));
                float n = tanhf(i_n + r*h_n);
                float hp = sh[b*SB + j];
                float hv = (1.f - z)*n + z*hp;
                g_hall[l][t+1][b][j] = hv;
                if (l == Ld-1) g_cat[(b*Tlen + t)*CATW + 300 + j] = hv;
            }
        }
        grid_barrier();
        if (wf + 1 < Tlen + Ld - 1) {
            int wf2 = wf + 1;
            int l2 = wf2 - (Tlen-1); if (l2 < 0) l2 = 0;
            gru_prefetch(l2, wf2 - l2, tid, px, ph);
        }
    }
}

// ---------------------------------------------------------------------------
// Small GEMM (Q / FEAT only) — unchanged
// ---------------------------------------------------------------------------
#define MODE_Q    0
#define MODE_FEAT 1
#define TS 68

__global__ void __launch_bounds__(256) gemm_kernel(
        int mode, const float* __restrict__ W, const float* __restrict__ bias,
        int N, int K, int lda) {
    const float* A; float* C;
    if (mode == MODE_Q) { A = g_cat + 300; C = g_q; }
    else                { A = g_cat;       C = g_feat; }

    __shared__ __align__(16) float As[30*TS];
    __shared__ __align__(16) float Bs[30*TS];
    int tid = threadIdx.x;
    int tx = tid & 15, ty = tid >> 4;
    int row0 = blockIdx.y*64, col0 = blockIdx.x*64;

    unsigned long long acc[4][2];
    #pragma unroll
    for (int i = 0; i < 4; i++) { acc[i][0] = 0ull; acc[i][1] = 0ull; }

    for (int k0 = 0; k0 < K; k0 += 30) {
        for (int i = tid; i < 64*30; i += 256) {
            int m = i/30, k = i - m*30;
            As[k*TS + m] = A[(size_t)(row0+m)*lda + k0 + k];
            int col = col0 + m;
            Bs[k*TS + m] = (col < N) ? W[(size_t)col*K + k0 + k] : 0.f;
        }
        __syncthreads();
        #pragma unroll
        for (int k = 0; k < 30; k++) {
            float4 av = *(const float4*)&As[k*TS + ty*4];
            float4 bv = *(const float4*)&Bs[k*TS + tx*4];
            unsigned long long b01, b23;
            asm("mov.b64 %0, {%1,%2};" : "=l"(b01) : "f"(bv.x), "f"(bv.y));
            asm("mov.b64 %0, {%1,%2};" : "=l"(b23) : "f"(bv.z), "f"(bv.w));
            float aarr[4] = {av.x, av.y, av.z, av.w};
            #pragma unroll
            for (int i = 0; i < 4; i++) {
                unsigned long long ap;
                asm("mov.b64 %0, {%1,%1};" : "=l"(ap) : "f"(aarr[i]));
                FMA2(acc[i][0], ap, b01);
                FMA2(acc[i][1], ap, b23);
            }
        }
        __syncthreads();
    }
    #pragma unroll
    for (int i = 0; i < 4; i++) {
        int row = row0 + ty*4 + i;
        float c0,c1,c2,c3;
        asm("mov.b64 {%0,%1}, %2;" : "=f"(c0), "=f"(c1) : "l"(acc[i][0]));
        asm("mov.b64 {%0,%1}, %2;" : "=f"(c2), "=f"(c3) : "l"(acc[i][1]));
        int col = col0 + tx*4;
        float* crow = C + (size_t)row*N;
        if (col+0 < N) crow[col+0] = c0 + bias[col+0];
        if (col+1 < N) crow[col+1] = c1 + bias[col+1];
        if (col+2 < N) crow[col+2] = c2 + bias[col+2];
        if (col+3 < N) crow[col+3] = c3 + bias[col+3];
    }
}

// ---------------------------------------------------------------------------
// split helper: v -> (hi bf16, lo bf16 = bf16(v - hi)) packed as uint pairs
// ---------------------------------------------------------------------------
__device__ __forceinline__ void split4(float4 v, uint2& hh, uint2& ll) {
    __nv_bfloat16 h0 = __float2bfloat16(v.x), h1 = __float2bfloat16(v.y);
    __nv_bfloat16 h2 = __float2bfloat16(v.z), h3 = __float2bfloat16(v.w);
    __nv_bfloat162 p01, p23, q01, q23;
    p01.x = h0; p01.y = h1; p23.x = h2; p23.y = h3;
    q01.x = __float2bfloat16(v.x - __bfloat162float(h0));
    q01.y = __float2bfloat16(v.y - __bfloat162float(h1));
    q23.x = __float2bfloat16(v.z - __bfloat162float(h2));
    q23.y = __float2bfloat16(v.w - __bfloat162float(h3));
    hh.x = *(unsigned*)&p01; hh.y = *(unsigned*)&p23;
    ll.x = *(unsigned*)&q01; ll.y = *(unsigned*)&q23;
}

// ---------------------------------------------------------------------------
// MMA out-GEMM v3: fp32 sources split to bf16 hi/lo in-register during
// staging (no convert kernels); fragments via ldmatrix; 3 products
// (hh + lh + hl) into fp32 accumulators. Grid (4, 391), 256 thr (8 warps =
// 2M x 4N, warp tile 64x32). Epilogue: exp(+bias) -> g_logits + row sums.
// ---------------------------------------------------------------------------
__global__ void __launch_bounds__(256) out_gemm_mma_kernel(
        const float* __restrict__ W, const float* __restrict__ bias) {
    __shared__ __align__(16) __nv_bfloat16 sAh[128*SA];
    __shared__ __align__(16) __nv_bfloat16 sAl[128*SA];
    __shared__ __align__(16) __nv_bfloat16 sBh[128*SA];
    __shared__ __align__(16) __nv_bfloat16 sBl[128*SA];
    __shared__ float sbias[128];

    const int tid = threadIdx.x;
    const int wid = tid >> 5, lane = tid & 31;
    const int g = lane >> 2, q = lane & 3;
    const int wm = wid & 1, wn = wid >> 1;
    const int row0 = blockIdx.x * 128;
    const int col0 = blockIdx.y * 128;

    if (tid < 128) {
        int c = col0 + tid;
        sbias[tid] = (c < Vocab) ? bias[c] : 0.f;
    }

    // ldmatrix lane addressing (bytes), computed once
    const unsigned baseAh = smem_u32(sAh), baseAl = smem_u32(sAl);
    const unsigned baseBh = smem_u32(sBh), baseBl = smem_u32(sBl);
    const unsigned offA = (unsigned)(((wm*64 + (lane & 15))*SA + (lane >> 4)*8) * 2);
    const unsigned offB = (unsigned)(((wn*32 + (lane & 7))*SA + ((lane >> 3) & 1)*8) * 2);

    float acc[4][4][4];
    #pragma unroll
    for (int mf = 0; mf < 4; mf++)
        #pragma unroll
        for (int nf = 0; nf < 4; nf++)
            #pragma unroll
            for (int e = 0; e < 4; e++) acc[mf][nf][e] = 0.f;

    for (int kt = 0; kt < 10; kt++) {
        int k0 = kt * 32;
        if (kt) __syncthreads();
        // stage: read fp32, split in-register, STS hi/lo (8 float4 per 32-k row)
        for (int i = tid; i < 1024; i += 256) {
            int r = i >> 3, c4 = (i & 7) * 4;
            int k = k0 + c4;
            float4 av = make_float4(0.f,0.f,0.f,0.f);
            float4 bv = make_float4(0.f,0.f,0.f,0.f);
            if (k < Hd) {   // K=300 is 4-aligned: float4 fully valid or fully OOB
                av = *(const float4*)(g_feat + (size_t)(row0 + r)*Hd + k);
                int col = col0 + r;
                if (col < Vocab)
                    bv = *(const float4*)(W + (size_t)col*Hd + k);
            }
            uint2 hh, ll;
            split4(av, hh, ll);
            *(uint2*)&sAh[r*SA + c4] = hh;
            *(uint2*)&sAl[r*SA + c4] = ll;
            split4(bv, hh, ll);
            *(uint2*)&sBh[r*SA + c4] = hh;
            *(uint2*)&sBl[r*SA + c4] = ll;
        }
        __syncthreads();

        #pragma unroll
        for (int kk = 0; kk < 32; kk += 16) {
            unsigned ah[4][4], al[4][4], bh[4][2], bl[4][2];
            #pragma unroll
            for (int mf = 0; mf < 4; mf++) {
                unsigned o = offA + (unsigned)((mf*16*SA + kk) * 2);
                LDSM_X4(ah[mf], baseAh + o);
                LDSM_X4(al[mf], baseAl + o);
            }
            #pragma unroll
            for (int nf = 0; nf < 4; nf++) {
                unsigned o = offB + (unsigned)((nf*8*SA + kk) * 2);
                LDSM_X2(bh[nf], baseBh + o);
                LDSM_X2(bl[nf], baseBl + o);
            }
            #pragma unroll
            for (int mf = 0; mf < 4; mf++)
                #pragma unroll
                for (int nf = 0; nf < 4; nf++) {
                    MMA_BF16(acc[mf][nf], ah[mf], bh[nf]);
                    MMA_BF16(acc[mf][nf], al[mf], bh[nf]);
                    MMA_BF16(acc[mf][nf], ah[mf], bl[nf]);
                }
        }
    }
    __syncthreads();

    // epilogue: exp + store + quad-reduced row sums
    #pragma unroll
    for (int mf = 0; mf < 4; mf++) {
        #pragma unroll
        for (int h = 0; h < 2; h++) {
            int row = row0 + wm*64 + mf*16 + h*8 + g;
            float s = 0.f;
            #pragma unroll
            for (int nf = 0; nf < 4; nf++) {
                int cl = wn*32 + nf*8 + 2*q;
                int col = col0 + cl;
                float e0 = 0.f, e1 = 0.f;
                if (col < Vocab) {
                    e0 = __expf(acc[mf][nf][h*2+0] + sbias[cl]);
                    e1 = __expf(acc[mf][nf][h*2+1] + sbias[cl+1]);
                    *(float2*)&g_logits[(size_t)row*Vocab + col] = make_float2(e0, e1);
                }
                s += e0 + e1;
            }
            s += __shfl_xor_sync(0xffffffffu, s, 1);
            s += __shfl_xor_sync(0xffffffffu, s, 2);
            if (q == 0) atomicAdd(&g_rowsum[row], s);
        }
    }
}

// ---------------------------------------------------------------------------
// Attention v2: one block per (b, t-half). src staged into smem once per
// chunk and shared by 8 t's -> src L2 traffic drops ~16x. 64 blocks, 256 thr
// (warp = one t). Dynamic smem (ATT_BYTES).
// ---------------------------------------------------------------------------
__global__ void __launch_bounds__(256) attn_kernel(
        const float* __restrict__ src, const void* __restrict__ maskp,
        float* __restrict__ attn_out) {
    float* sq   = s_dyn + AQ_OFF;     // [8][304]
    float* ssc  = s_dyn + ASC_OFF;    // [8][400] scores -> probs
    float* ssrc = s_dyn + ASRC_OFF;   // [32][308]

    const int tid = threadIdx.x, lane = tid & 31, w = tid >> 5;
    const int b  = blockIdx.x >> 1;
    const int th = blockIdx.x & 1;
    const int tg = th*8 + w;                 // global t for this warp
    const int row = b*Tlen + tg;

    const unsigned char* m8  = (const unsigned char*)maskp;
    const int*           m32 = (const int*)maskp;
    const int useu8 = g_mask_u8;

    // load q rows (8 x 300)
    for (int i = tid; i < 8*Hd; i += 256) {
        int t = i / Hd, hh = i - t*Hd;
        sq[t*304 + hh] = g_q[(b*Tlen + th*8 + t)*Hd + hh];
    }
    __syncthreads();

    // ---- scores ----
    for (int s0 = 0; s0 < Slen; s0 += 32) {
        if (s0) __syncthreads();
        for (int i = tid; i < 32*75; i += 256) {
            int s = i / 75, q4 = (i - s*75)*4;
            if (s0 + s < Slen)
                *(float4*)&ssrc[s*SB + q4] =
                    *(const float4*)(src + ((size_t)b*Slen + s0 + s)*Hd + q4);
        }
        __syncthreads();
        int s = s0 + lane;
        if (s < Slen) {
            const float* qp = &sq[w*304];
            const float* sp = &ssrc[lane*SB];
            float a0 = 0.f, a1 = 0.f, a2 = 0.f, a3 = 0.f;
            #pragma unroll 5
            for (int h4 = 0; h4 < Hd; h4 += 4) {
                float4 qv = *(const float4*)(qp + h4);   // broadcast
                float4 sv = *(const float4*)(sp + h4);
                a0 += qv.x*sv.x; a1 += qv.y*sv.y;
                a2 += qv.z*sv.z; a3 += qv.w*sv.w;
            }
            int mk = useu8 ? (int)m8[b*Slen + s] : m32[b*Slen + s];
            ssc[w*400 + s] = mk ? ((a0+a1) + (a2+a3)) : -1e9f;
        }
    }
    __syncthreads();

    // ---- softmax (warp-local over 400) + write attn_out ----
    {
        float mv = -3.4e38f;
        for (int s = lane; s < Slen; s += 32) mv = fmaxf(mv, ssc[w*400 + s]);
        #pragma unroll
        for (int o = 16; o; o >>= 1) mv = fmaxf(mv, __shfl_xor_sync(0xffffffffu, mv, o));
        float sv = 0.f;
        for (int s = lane; s < Slen; s += 32) {
            float e = __expf(ssc[w*400 + s] - mv);
            ssc[w*400 + s] = e;
            sv += e;
        }
        #pragma unroll
        for (int o = 16; o; o >>= 1) sv += __shfl_xor_sync(0xffffffffu, sv, o);
        float inv = 1.f / sv;
        for (int s = lane; s < Slen; s += 32) {
            float pn = ssc[w*400 + s] * inv;
            ssc[w*400 + s] = pn;                            // normalized probs
            attn_out[(size_t)row*Slen + s] = pn;
        }
    }
    __syncwarp();

    // ---- contexts: ctx[t][h] = sum_s p[t][s] * src[s][h] ----
    float4 c0 = make_float4(0.f,0.f,0.f,0.f);
    float4 c1 = make_float4(0.f,0.f,0.f,0.f);
    float4 c2 = make_float4(0.f,0.f,0.f,0.f);
    const int h2 = 256 + lane*4;          // third segment (partial)
    for (int s0 = 0; s0 < Slen; s0 += 32) {
        __syncthreads();                   // drain previous chunk's readers (and softmax)
        for (int i = tid; i < 32*75; i += 256) {
            int s = i / 75, q4 = (i - s*75)*4;
            if (s0 + s < Slen)
                *(float4*)&ssrc[s*SB + q4] =
                    *(const float4*)(src + ((size_t)b*Slen + s0 + s)*Hd + q4);
        }
        __syncthreads();
        int smax = Slen - s0; if (smax > 32) smax = 32;
        for (int ss = 0; ss < smax; ss++) {
            float pp = ssc[w*400 + s0 + ss];               // broadcast
            const float* sp = &ssrc[ss*SB];
            float4 v0 = *(const float4*)(sp + lane*4);
            float4 v1 = *(const float4*)(sp + 128 + lane*4);
            c0.x += pp*v0.x; c0.y += pp*v0.y; c0.z += pp*v0.z; c0.w += pp*v0.w;
            c1.x += pp*v1.x; c1.y += pp*v1.y; c1.z += pp*v1.z; c1.w += pp*v1.w;
            if (h2 < Hd) {
                float4 v2 = *(const float4*)(sp + h2);
                c2.x += pp*v2.x; c2.y += pp*v2.y; c2.z += pp*v2.z; c2.w += pp*v2.w;
            }
        }
    }
    *(float4*)&g_cat[row*CATW + lane*4]       = c0;
    *(float4*)&g_cat[row*CATW + 128 + lane*4] = c1;
    if (h2 < Hd) *(float4*)&g_cat[row*CATW + h2] = c2;
}

// ---------------------------------------------------------------------------
// p_gen (unchanged)
// ---------------------------------------------------------------------------
__global__ void pgen_kernel(const float* __restrict__ pW,
                            const float* __restrict__ pb) {
    int wg = blockIdx.x*(blockDim.x >> 5) + (threadIdx.x >> 5);
    if (wg >= ROWS) return;
    int lane = threadIdx.x & 31;
    const float* crow = g_cat + wg*CATW;
    float a0 = 0.f, a1 = 0.f;
    for (int k = lane; k < CATW; k += 32) {
        float v = crow[k];
        a0 += v*pW[k];
        a1 += v*pW[CATW + k];
    }
    #pragma unroll
    for (int o = 16; o; o >>= 1) {
        a0 += __shfl_xor_sync(0xffffffffu, a0, o);
        a1 += __shfl_xor_sync(0xffffffffu, a1, o);
    }
    if (lane == 0) {
        float l0 = a0 + pb[0], l1 = a1 + pb[1];
        float m = fmaxf(l0, l1);
        float e0 = __expf(l0 - m), e1 = __expf(l1 - m);
        float inv = 1.f/(e0 + e1);
        g_pgen[wg*2+0] = e0*inv;
        g_pgen[wg*2+1] = e1*inv;
    }
}

// ---------------------------------------------------------------------------
// Merged final scale + copy scatter (unchanged)
// ---------------------------------------------------------------------------
__global__ void __launch_bounds__(256) scale_scatter_kernel(
        float* __restrict__ out, const int* __restrict__ src_oov,
        const float* __restrict__ attn) {
    int row = blockIdx.x;
    int b = row / Tlen;
    float scale = g_pgen[row*2] / g_rowsum[row];
    const float* lrow = g_logits + (size_t)row*Vocab;
    float* orow = out + (size_t)row*VO;
    for (int v = threadIdx.x; v < VO; v += 256)
        orow[v] = (v < Vocab) ? scale*lrow[v] : 0.f;
    __syncthreads();
    float p1 = g_pgen[row*2+1];
    for (int s = threadIdx.x; s < Slen; s += 256) {
        float a = attn[(size_t)row*Slen + s] * p1;
        int col = src_oov[b*Slen + s];
        atomicAdd(&orow[col], a);
    }
}

// ---------------------------------------------------------------------------
// Host launcher
// ---------------------------------------------------------------------------
extern "C" void kernel_launch(void* const* d_in, const int* in_sizes, int n_in,
                              void* d_out, int out_size) {
    int idx = 0;
    const int*   tokens  = (const int*)  d_in[idx++];
    const float* src     = (const float*)d_in[idx++];
    const void*  mask    =               d_in[idx++];
    const float* hidden0 = (const float*)d_in[idx++];
    const int*   src_oov = (const int*)  d_in[idx++];
    if (idx < n_in && in_sizes[idx] == 1) idx++;   // max_num_oov scalar
    const float* embed   = (const float*)d_in[idx++];
    const float* W_ih    = (const float*)d_in[idx++];
    const float* W_hh    = (const float*)d_in[idx++];
    const float* b_ih    = (const float*)d_in[idx++];
    const float* b_hh    = (const float*)d_in[idx++];
    const float* attn_W  = (const float*)d_in[idx++];
    const float* attn_b  = (const float*)d_in[idx++];
    const float* fc_W    = (const float*)d_in[idx++];
    const float* fc_b    = (const float*)d_in[idx++];
    const float* out_W   = (const float*)d_in[idx++];
    const float* out_b   = (const float*)d_in[idx++];
    const float* pgen_W  = (const float*)d_in[idx++];
    const float* pgen_b  = (const float*)d_in[idx++];

    float* out = (float*)d_out;
    float* attn_out;
    if (out_size >= (int)((size_t)ROWS*VO + (size_t)ROWS*Slen)) {
        attn_out = out + (size_t)ROWS*VO;
    } else {
        void* p = nullptr;
        cudaGetSymbolAddress(&p, g_attn_fallback);
        attn_out = (float*)p;
    }

    cudaFuncSetAttribute(gru_persistent_kernel,
                         cudaFuncAttributeMaxDynamicSharedMemorySize, SMEM_BYTES);
    cudaFuncSetAttribute(attn_kernel,
                         cudaFuncAttributeMaxDynamicSharedMemorySize, ATT_BYTES);

    detect_mask_kernel<<<1,1>>>((const unsigned char*)mask);
    init_hall_kernel<<<(Ld*Bsz*Hd+255)/256,256>>>(hidden0);
    embed_kernel<<<(ROWS*Ed+255)/256,256>>>(tokens, embed);

    gru_persistent_kernel<<<NBLK, NTHR, SMEM_BYTES>>>(W_ih, W_hh, b_ih, b_hh);

    gemm_kernel<<<dim3(5,8),256>>>(MODE_Q, attn_W, attn_b, Hd, Hd, CATW);
    attn_kernel<<<64,256, ATT_BYTES>>>(src, mask, attn_out);
    gemm_kernel<<<dim3(5,8),256>>>(MODE_FEAT, fc_W, fc_b, Hd, 2*Hd, CATW);
    pgen_kernel<<<64,256>>>(pgen_W, pgen_b);

    out_gemm_mma_kernel<<<dim3(4,391),256>>>(out_W, out_b);
    scale_scatter_kernel<<<ROWS,256>>>(out, src_oov, attn_out);
}

// round 16
// speedup vs baseline: 1.1355x; 1.1355x over previous
#include <cuda_runtime.h>
#include <cuda_bf16.h>
#include <math.h>

// ---------------------------------------------------------------------------
// Problem constants
// ---------------------------------------------------------------------------
#define Bsz   32
#define Tlen  16
#define Slen  400
#define Hd    300
#define Ed    300
#define Ld    3
#define Vocab 50000
#define OOV   20
#define ROWS  (Bsz*Tlen)      // 512
#define VO    (Vocab+OOV)     // 50020
#define CATW  900             // [contexts(300) | hiddens(300) | x(300)]

// Persistent GRU config
#define NBLK  100
#define NTHR  864
#define NJ    3
#define SB    308

// GRU smem layout (floats)
#define SW_FLOATS   16200
#define SX_OFF      16200
#define SH_OFF      (SX_OFF + Bsz*SB)
#define SACC_OFF    (SH_OFF + Bsz*SB)
#define SBIAS_OFF   (SACC_OFF + 18*96)
#define SMEM_FLOATS (SBIAS_OFF + 54)
#define SMEM_BYTES  (SMEM_FLOATS*4)

#define FMA2(acc, x, y) asm("fma.rn.f32x2 %0, %1, %2, %0;" : "+l"(acc) : "l"(x), "l"(y))

// MMA out-GEMM config (R14-proven: pre-split arrays + scalar frag loads)
#define KP     320            // K padded: 10 chunks of 32 (300 real + 20 zero)
#define BROWS  50048          // vocab padded to 391*128
#define SA     40             // smem tile stride in bf16

#define MMA_BF16(c, a, b) \
    asm volatile("mma.sync.aligned.m16n8k16.row.col.f32.bf16.bf16.f32 " \
        "{%0,%1,%2,%3}, {%4,%5,%6,%7}, {%8,%9}, {%0,%1,%2,%3};" \
        : "+f"((c)[0]), "+f"((c)[1]), "+f"((c)[2]), "+f"((c)[3]) \
        : "r"((a)[0]), "r"((a)[1]), "r"((a)[2]), "r"((a)[3]), \
          "r"((b)[0]), "r"((b)[1]))

// attn v2 smem layout (floats): q[8][304] | probs[8][400] | src chunk [32][308]
#define AQ_OFF    0
#define ASC_OFF   2432
#define ASRC_OFF  (2432 + 3200)            // 5632
#define ATT_FLOATS (5632 + 32*308)         // 15488
#define ATT_BYTES  (ATT_FLOATS*4)          // 61952

// ---------------------------------------------------------------------------
// Scratch
// ---------------------------------------------------------------------------
__device__ float g_cat[ROWS*CATW];
__device__ float g_hall[Ld][Tlen+1][Bsz][Hd];
__device__ float g_q[ROWS*Hd];
__device__ float g_feat[ROWS*Hd];
__device__ float g_logits[(size_t)ROWS*Vocab];     // exp(logit) after out-GEMM
__device__ float g_rowsum[ROWS];
__device__ float g_pgen[ROWS*2];
__device__ float g_attn_fallback[ROWS*Slen];
__device__ int   g_mask_u8;
// split-bf16 operands for the MMA out-GEMM
__device__ __nv_bfloat16 g_Ah[ROWS*KP];
__device__ __nv_bfloat16 g_Al[ROWS*KP];
__device__ __nv_bfloat16 g_Bh[(size_t)BROWS*KP];
__device__ __nv_bfloat16 g_Bl[(size_t)BROWS*KP];

__device__ unsigned g_bar_cnt = 0;
__device__ unsigned g_bar_gen = 0;

// ---------------------------------------------------------------------------
__global__ void detect_mask_kernel(const unsigned char* __restrict__ m) {
    g_mask_u8 = (m[1] | m[2] | m[3]) ? 1 : 0;
}

__global__ void init_hall_kernel(const float* __restrict__ h0) {
    int i = blockIdx.x*blockDim.x + threadIdx.x;
    if (i < Ld*Bsz*Hd) {
        int l = i / (Bsz*Hd), r = i - l*(Bsz*Hd);
        (&g_hall[l][0][0][0])[r] = h0[i];
    }
    if (i < ROWS) g_rowsum[i] = 0.f;
}

__global__ void embed_kernel(const int* __restrict__ tokens,
                             const float* __restrict__ embed) {
    int i = blockIdx.x*blockDim.x + threadIdx.x;
    if (i < ROWS*Ed) {
        int row = i / Ed, e = i - row*Ed;
        g_cat[row*CATW + 600 + e] = embed[(size_t)tokens[row]*Ed + e];
    }
}

// ---------------------------------------------------------------------------
// Grid barrier
// ---------------------------------------------------------------------------
__device__ __forceinline__ void grid_barrier() {
    __threadfence();
    __syncthreads();
    if (threadIdx.x == 0) {
        unsigned gen = *(volatile unsigned*)&g_bar_gen;
        if (atomicAdd(&g_bar_cnt, 1u) == NBLK - 1u) {
            atomicExch(&g_bar_cnt, 0u);
            __threadfence();
            atomicAdd(&g_bar_gen, 1u);
        } else {
            while (*(volatile unsigned*)&g_bar_gen == gen) __nanosleep(32);
        }
        __threadfence();
    }
    __syncthreads();
}

// ---------------------------------------------------------------------------
// GRU activation prefetch (registers)
// ---------------------------------------------------------------------------
__device__ __forceinline__ void gru_prefetch(int l, int t, int tid,
                                             float4* px, float4* ph) {
    const float* xsrc; size_t xstr;
    if (l == 0) { xsrc = g_cat + t*CATW + 600; xstr = Tlen*CATW; }
    else        { xsrc = &g_hall[l-1][t+1][0][0]; xstr = Hd; }
    const float* hsrc = &g_hall[l][t][0][0];
    #pragma unroll
    for (int it = 0; it < 3; it++) {
        int i = tid + it*NTHR;
        if (i < Bsz*75) {
            int b = i / 75, q4 = (i - b*75)*4;
            px[it] = *(const float4*)(xsrc + (size_t)b*xstr + q4);
            ph[it] = *(const float4*)(hsrc + b*Hd + q4);
        }
    }
}

// ---------------------------------------------------------------------------
// Persistent GRU v5.1 (unchanged — R12/R14 proven)
// ---------------------------------------------------------------------------
extern __shared__ float s_dyn[];

__global__ void __launch_bounds__(NTHR) gru_persistent_kernel(
        const float* __restrict__ W_ih, const float* __restrict__ W_hh,
        const float* __restrict__ b_ih, const float* __restrict__ b_hh) {
    float* sw   = s_dyn;
    float* sx   = s_dyn + SX_OFF;
    float* sh   = s_dyn + SH_OFF;
    float* sacc = s_dyn + SACC_OFF;
    float* sb   = s_dyn + SBIAS_OFF;

    const int tid  = threadIdx.x;
    const int j0   = blockIdx.x * NJ;
    const int lane = tid & 31, w = tid >> 5;
    const int p = w / 3, q = w - 3*p;
    const int tA = 2*p, tB = tA + 1;
    const int kbeg = q * 100;

    for (int idx = tid; idx < SW_FLOATS; idx += NTHR) {
        int l = idx / 5400, r = idx - l*5400;
        int task = r / 300, k = r - task*300;
        int m = task / 9, t2 = task - m*9;
        int g = t2 / 3, jl = t2 - g*3;
        int row = g*300 + j0 + jl;
        const float* src = (m == 0) ? W_ih : W_hh;
        sw[idx] = src[(size_t)l*270000 + (size_t)row*300 + k];
    }
    if (tid < 54) {
        int l = tid / 18, r = tid % 18;
        int m = r / 9, r2 = r % 9;
        int g = r2 / 3, jl = r2 % 3;
        const float* src = m ? b_hh : b_ih;
        sb[tid] = src[l*900 + g*300 + j0 + jl];
    }

    float4 px[3], ph[3];
    gru_prefetch(0, 0, tid, px, ph);

    for (int wf = 0; wf < Tlen + Ld - 1; wf++) {
        int lmin = wf - (Tlen-1); if (lmin < 0) lmin = 0;
        int lmax = (wf < Ld-1) ? wf : Ld-1;
        for (int l = lmin; l <= lmax; l++) {
            int t = wf - l;

            if (l != lmin) __syncthreads();

            #pragma unroll
            for (int it = 0; it < 3; it++) {
                int i = tid + it*NTHR;
                if (i < Bsz*75) {
                    int b = i / 75, q4 = (i - b*75)*4;
                    *(float4*)&sx[b*SB + q4] = px[it];
                    *(float4*)&sh[b*SB + q4] = ph[it];
                }
            }
            __syncthreads();

            if (l < lmax) gru_prefetch(l+1, t-1, tid, px, ph);

            {
                const float* wA = sw + (l*18 + tA)*300;
                const float* wB = sw + (l*18 + tB)*300;
                const float* aA = ((tA < 9) ? sx : sh) + lane*SB;
                const float* aB = ((tB < 9) ? sx : sh) + lane*SB;
                unsigned long long accA0 = 0ull, accA1 = 0ull;
                unsigned long long accB0 = 0ull, accB1 = 0ull;
                if (p != 4) {
                    #pragma unroll 4
                    for (int kk = 0; kk < 96; kk += 8) {
                        int k = kbeg + kk;
                        ulonglong2 wa0 = *(const ulonglong2*)(wA + k);
                        ulonglong2 wa1 = *(const ulonglong2*)(wA + k + 4);
                        ulonglong2 wb0 = *(const ulonglong2*)(wB + k);
                        ulonglong2 wb1 = *(const ulonglong2*)(wB + k + 4);
                        ulonglong2 x01 = *(const ulonglong2*)(aA + k);
                        ulonglong2 x23 = *(const ulonglong2*)(aA + k + 4);
                        FMA2(accA0, wa0.x, x01.x); FMA2(accA1, wa0.y, x01.y);
                        FMA2(accB0, wb0.x, x01.x); FMA2(accB1, wb0.y, x01.y);
                        FMA2(accA0, wa1.x, x23.x); FMA2(accA1, wa1.y, x23.y);
                        FMA2(accB0, wb1.x, x23.x); FMA2(accB1, wb1.y, x23.y);
                    }
                    {
                        int k = kbeg + 96;
                        ulonglong2 wa = *(const ulonglong2*)(wA + k);
                        ulonglong2 wb = *(const ulonglong2*)(wB + k);
                        ulonglong2 x01 = *(const ulonglong2*)(aA + k);
                        FMA2(accA0, wa.x, x01.x); FMA2(accA1, wa.y, x01.y);
                        FMA2(accB0, wb.x, x01.x); FMA2(accB1, wb.y, x01.y);
                    }
                } else {
                    #pragma unroll 4
                    for (int kk = 0; kk < 96; kk += 8) {
                        int k = kbeg + kk;
                        ulonglong2 wa0 = *(const ulonglong2*)(wA + k);
                        ulonglong2 wa1 = *(const ulonglong2*)(wA + k + 4);
                        ulonglong2 wb0 = *(const ulonglong2*)(wB + k);
                        ulonglong2 wb1 = *(const ulonglong2*)(wB + k + 4);
                        ulonglong2 x01 = *(const ulonglong2*)(aA + k);
                        ulonglong2 x23 = *(const ulonglong2*)(aA + k + 4);
                        ulonglong2 y01 = *(const ulonglong2*)(aB + k);
                        ulonglong2 y23 = *(const ulonglong2*)(aB + k + 4);
                        FMA2(accA0, wa0.x, x01.x); FMA2(accA1, wa0.y, x01.y);
                        FMA2(accB0, wb0.x, y01.x); FMA2(accB1, wb0.y, y01.y);
                        FMA2(accA0, wa1.x, x23.x); FMA2(accA1, wa1.y, x23.y);
                        FMA2(accB0, wb1.x, y23.x); FMA2(accB1, wb1.y, y23.y);
                    }
                    {
                        int k = kbeg + 96;
                        ulonglong2 wa = *(const ulonglong2*)(wA + k);
                        ulonglong2 wb = *(const ulonglong2*)(wB + k);
                        ulonglong2 x01 = *(const ulonglong2*)(aA + k);
                        ulonglong2 y01 = *(const ulonglong2*)(aB + k);
                        FMA2(accA0, wa.x, x01.x); FMA2(accA1, wa.y, x01.y);
                        FMA2(accB0, wb.x, y01.x); FMA2(accB1, wb.y, y01.y);
                    }
                }
                float a0,a1,a2,a3;
                asm("mov.b64 {%0,%1}, %2;" : "=f"(a0), "=f"(a1) : "l"(accA0));
                asm("mov.b64 {%0,%1}, %2;" : "=f"(a2), "=f"(a3) : "l"(accA1));
                sacc[tA*96 + q*32 + lane] = (a0+a1) + (a2+a3);
                asm("mov.b64 {%0,%1}, %2;" : "=f"(a0), "=f"(a1) : "l"(accB0));
                asm("mov.b64 {%0,%1}, %2;" : "=f"(a2), "=f"(a3) : "l"(accB1));
                sacc[tB*96 + q*32 + lane] = (a0+a1) + (a2+a3);
            }
            __syncthreads();

            if (tid < 96) {
                int b = tid & 31, jl = tid >> 5;
                int j = j0 + jl;
                #define SAC(tk) (sacc[(tk)*96+b] + sacc[(tk)*96+32+b] + sacc[(tk)*96+64+b])
                float i_r = SAC( 0+jl) + sb[l*18 +      jl];
                float i_z = SAC( 3+jl) + sb[l*18 +  3 + jl];
                float i_n = SAC( 6+jl) + sb[l*18 +  6 + jl];
                float h_r = SAC( 9+jl) + sb[l*18 +  9 + jl];
                float h_z = SAC(12+jl) + sb[l*18 + 12 + jl];
                float h_n = SAC(15+jl) + sb[l*18 + 15 + jl];
                #undef SAC
                float r = 1.f/(1.f + __expf(-(i_r + h_r)));
                float z = 1.f/(1.f + __expf(-(i_z + h_z)));
                float n = tanhf(i_n + r*h_n);
                float hp = sh[b*SB + j];
                float hv = (1.f - z)*n + z*hp;
                g_hall[l][t+1][b][j] = hv;
                if (l == Ld-1) g_cat[(b*Tlen + t)*CATW + 300 + j] = hv;
            }
        }
        grid_barrier();
        if (wf + 1 < Tlen + Ld - 1) {
            int wf2 = wf + 1;
            int l2 = wf2 - (Tlen-1); if (l2 < 0) l2 = 0;
            gru_prefetch(l2, wf2 - l2, tid, px, ph);
        }
    }
}

// ---------------------------------------------------------------------------
// Small GEMM (Q / FEAT only) — unchanged
// ---------------------------------------------------------------------------
#define MODE_Q    0
#define MODE_FEAT 1
#define TS 68

__global__ void __launch_bounds__(256) gemm_kernel(
        int mode, const float* __restrict__ W, const float* __restrict__ bias,
        int N, int K, int lda) {
    const float* A; float* C;
    if (mode == MODE_Q) { A = g_cat + 300; C = g_q; }
    else                { A = g_cat;       C = g_feat; }

    __shared__ __align__(16) float As[30*TS];
    __shared__ __align__(16) float Bs[30*TS];
    int tid = threadIdx.x;
    int tx = tid & 15, ty = tid >> 4;
    int row0 = blockIdx.y*64, col0 = blockIdx.x*64;

    unsigned long long acc[4][2];
    #pragma unroll
    for (int i = 0; i < 4; i++) { acc[i][0] = 0ull; acc[i][1] = 0ull; }

    for (int k0 = 0; k0 < K; k0 += 30) {
        for (int i = tid; i < 64*30; i += 256) {
            int m = i/30, k = i - m*30;
            As[k*TS + m] = A[(size_t)(row0+m)*lda + k0 + k];
            int col = col0 + m;
            Bs[k*TS + m] = (col < N) ? W[(size_t)col*K + k0 + k] : 0.f;
        }
        __syncthreads();
        #pragma unroll
        for (int k = 0; k < 30; k++) {
            float4 av = *(const float4*)&As[k*TS + ty*4];
            float4 bv = *(const float4*)&Bs[k*TS + tx*4];
            unsigned long long b01, b23;
            asm("mov.b64 %0, {%1,%2};" : "=l"(b01) : "f"(bv.x), "f"(bv.y));
            asm("mov.b64 %0, {%1,%2};" : "=l"(b23) : "f"(bv.z), "f"(bv.w));
            float aarr[4] = {av.x, av.y, av.z, av.w};
            #pragma unroll
            for (int i = 0; i < 4; i++) {
                unsigned long long ap;
                asm("mov.b64 %0, {%1,%1};" : "=l"(ap) : "f"(aarr[i]));
                FMA2(acc[i][0], ap, b01);
                FMA2(acc[i][1], ap, b23);
            }
        }
        __syncthreads();
    }
    #pragma unroll
    for (int i = 0; i < 4; i++) {
        int row = row0 + ty*4 + i;
        float c0,c1,c2,c3;
        asm("mov.b64 {%0,%1}, %2;" : "=f"(c0), "=f"(c1) : "l"(acc[i][0]));
        asm("mov.b64 {%0,%1}, %2;" : "=f"(c2), "=f"(c3) : "l"(acc[i][1]));
        int col = col0 + tx*4;
        float* crow = C + (size_t)row*N;
        if (col+0 < N) crow[col+0] = c0 + bias[col+0];
        if (col+1 < N) crow[col+1] = c1 + bias[col+1];
        if (col+2 < N) crow[col+2] = c2 + bias[col+2];
        if (col+3 < N) crow[col+3] = c3 + bias[col+3];
    }
}

// ---------------------------------------------------------------------------
// Split-bf16 conversion kernels (hi = bf16(v), lo = bf16(v - hi)) — R14
// ---------------------------------------------------------------------------
__global__ void convertA_kernel() {
    int i = blockIdx.x*blockDim.x + threadIdx.x;      // pairs
    if (i >= ROWS*(KP/2)) return;
    int r = i / (KP/2), kp = (i - r*(KP/2))*2;
    float v0 = (kp   < Hd) ? g_feat[r*Hd + kp  ] : 0.f;
    float v1 = (kp+1 < Hd) ? g_feat[r*Hd + kp+1] : 0.f;
    __nv_bfloat16 h0 = __float2bfloat16(v0), h1 = __float2bfloat16(v1);
    __nv_bfloat162 hh; hh.x = h0; hh.y = h1;
    __nv_bfloat162 ll;
    ll.x = __float2bfloat16(v0 - __bfloat162float(h0));
    ll.y = __float2bfloat16(v1 - __bfloat162float(h1));
    *(__nv_bfloat162*)&g_Ah[r*KP + kp] = hh;
    *(__nv_bfloat162*)&g_Al[r*KP + kp] = ll;
}

__global__ void convertB_kernel(const float* __restrict__ W) {
    int i = blockIdx.x*blockDim.x + threadIdx.x;      // pairs
    if (i >= BROWS*(KP/2)) return;
    int r = i / (KP/2), kp = (i - r*(KP/2))*2;
    float v0 = 0.f, v1 = 0.f;
    if (r < Vocab) {
        if (kp   < Hd) v0 = W[(size_t)r*Hd + kp  ];
        if (kp+1 < Hd) v1 = W[(size_t)r*Hd + kp+1];
    }
    __nv_bfloat16 h0 = __float2bfloat16(v0), h1 = __float2bfloat16(v1);
    __nv_bfloat162 hh; hh.x = h0; hh.y = h1;
    __nv_bfloat162 ll;
    ll.x = __float2bfloat16(v0 - __bfloat162float(h0));
    ll.y = __float2bfloat16(v1 - __bfloat162float(h1));
    *(__nv_bfloat162*)&g_Bh[(size_t)r*KP + kp] = hh;
    *(__nv_bfloat162*)&g_Bl[(size_t)r*KP + kp] = ll;
}

// ---------------------------------------------------------------------------
// MMA out-GEMM (R14-proven): split-bf16 mma.sync, scalar frag loads.
// Grid (4, 391), 256 thr (8 warps = 2M x 4N, warp tile 64x32).
// ---------------------------------------------------------------------------
__global__ void __launch_bounds__(256) out_gemm_mma_kernel(
        const float* __restrict__ bias) {
    __shared__ __align__(16) __nv_bfloat16 sAh[128*SA];
    __shared__ __align__(16) __nv_bfloat16 sAl[128*SA];
    __shared__ __align__(16) __nv_bfloat16 sBh[128*SA];
    __shared__ __align__(16) __nv_bfloat16 sBl[128*SA];
    __shared__ float sbias[128];

    const int tid = threadIdx.x;
    const int wid = tid >> 5, lane = tid & 31;
    const int g = lane >> 2, q = lane & 3;
    const int wm = wid & 1, wn = wid >> 1;
    const int row0 = blockIdx.x * 128;
    const int col0 = blockIdx.y * 128;

    if (tid < 128) {
        int c = col0 + tid;
        sbias[tid] = (c < Vocab) ? bias[c] : 0.f;
    }

    float acc[4][4][4];
    #pragma unroll
    for (int mf = 0; mf < 4; mf++)
        #pragma unroll
        for (int nf = 0; nf < 4; nf++)
            #pragma unroll
            for (int e = 0; e < 4; e++) acc[mf][nf][e] = 0.f;

    for (int kt = 0; kt < 10; kt++) {
        int k0 = kt * 32;
        if (kt) __syncthreads();
        for (int i = tid; i < 512; i += 256) {
            int r = i >> 2, c8 = (i & 3) * 8;
            size_t aoff = (size_t)(row0 + r)*KP + k0 + c8;
            size_t boff = (size_t)(col0 + r)*KP + k0 + c8;
            *(uint4*)&sAh[r*SA + c8] = *(const uint4*)(g_Ah + aoff);
            *(uint4*)&sAl[r*SA + c8] = *(const uint4*)(g_Al + aoff);
            *(uint4*)&sBh[r*SA + c8] = *(const uint4*)(g_Bh + boff);
            *(uint4*)&sBl[r*SA + c8] = *(const uint4*)(g_Bl + boff);
        }
        __syncthreads();

        #pragma unroll
        for (int kk = 0; kk < 32; kk += 16) {
            unsigned ah[4][4], al[4][4], bh[4][2], bl[4][2];
            #pragma unroll
            for (int mf = 0; mf < 4; mf++) {
                int base = (wm*64 + mf*16 + g)*SA + kk + 2*q;
                ah[mf][0] = *(const unsigned*)&sAh[base];
                ah[mf][1] = *(const unsigned*)&sAh[base + 8*SA];
                ah[mf][2] = *(const unsigned*)&sAh[base + 8];
                ah[mf][3] = *(const unsigned*)&sAh[base + 8*SA + 8];
                al[mf][0] = *(const unsigned*)&sAl[base];
                al[mf][1] = *(const unsigned*)&sAl[base + 8*SA];
                al[mf][2] = *(const unsigned*)&sAl[base + 8];
                al[mf][3] = *(const unsigned*)&sAl[base + 8*SA + 8];
            }
            #pragma unroll
            for (int nf = 0; nf < 4; nf++) {
                int base = (wn*32 + nf*8 + g)*SA + kk + 2*q;
                bh[nf][0] = *(const unsigned*)&sBh[base];
                bh[nf][1] = *(const unsigned*)&sBh[base + 8];
                bl[nf][0] = *(const unsigned*)&sBl[base];
                bl[nf][1] = *(const unsigned*)&sBl[base + 8];
            }
            #pragma unroll
            for (int mf = 0; mf < 4; mf++)
                #pragma unroll
                for (int nf = 0; nf < 4; nf++) {
                    MMA_BF16(acc[mf][nf], ah[mf], bh[nf]);
                    MMA_BF16(acc[mf][nf], al[mf], bh[nf]);
                    MMA_BF16(acc[mf][nf], ah[mf], bl[nf]);
                }
        }
    }
    __syncthreads();

    // epilogue: exp + store + quad-reduced row sums
    #pragma unroll
    for (int mf = 0; mf < 4; mf++) {
        #pragma unroll
        for (int h = 0; h < 2; h++) {
            int row = row0 + wm*64 + mf*16 + h*8 + g;
            float s = 0.f;
            #pragma unroll
            for (int nf = 0; nf < 4; nf++) {
                int cl = wn*32 + nf*8 + 2*q;
                int col = col0 + cl;
                float e0 = 0.f, e1 = 0.f;
                if (col < Vocab) {
                    e0 = __expf(acc[mf][nf][h*2+0] + sbias[cl]);
                    e1 = __expf(acc[mf][nf][h*2+1] + sbias[cl+1]);
                    *(float2*)&g_logits[(size_t)row*Vocab + col] = make_float2(e0, e1);
                }
                s += e0 + e1;
            }
            s += __shfl_xor_sync(0xffffffffu, s, 1);
            s += __shfl_xor_sync(0xffffffffu, s, 2);
            if (q == 0) atomicAdd(&g_rowsum[row], s);
        }
    }
}

// ---------------------------------------------------------------------------
// Attention v2 (R15-validated): one block per (b, t-half); src staged into
// smem once per chunk, shared by 8 t's. 64 blocks, 256 thr (warp = one t).
// ---------------------------------------------------------------------------
__global__ void __launch_bounds__(256) attn_kernel(
        const float* __restrict__ src, const void* __restrict__ maskp,
        float* __restrict__ attn_out) {
    float* sq   = s_dyn + AQ_OFF;     // [8][304]
    float* ssc  = s_dyn + ASC_OFF;    // [8][400] scores -> probs
    float* ssrc = s_dyn + ASRC_OFF;   // [32][308]

    const int tid = threadIdx.x, lane = tid & 31, w = tid >> 5;
    const int b  = blockIdx.x >> 1;
    const int th = blockIdx.x & 1;
    const int tg = th*8 + w;
    const int row = b*Tlen + tg;

    const unsigned char* m8  = (const unsigned char*)maskp;
    const int*           m32 = (const int*)maskp;
    const int useu8 = g_mask_u8;

    for (int i = tid; i < 8*Hd; i += 256) {
        int t = i / Hd, hh = i - t*Hd;
        sq[t*304 + hh] = g_q[(b*Tlen + th*8 + t)*Hd + hh];
    }
    __syncthreads();

    // ---- scores ----
    for (int s0 = 0; s0 < Slen; s0 += 32) {
        if (s0) __syncthreads();
        for (int i = tid; i < 32*75; i += 256) {
            int s = i / 75, q4 = (i - s*75)*4;
            if (s0 + s < Slen)
                *(float4*)&ssrc[s*SB + q4] =
                    *(const float4*)(src + ((size_t)b*Slen + s0 + s)*Hd + q4);
        }
        __syncthreads();
        int s = s0 + lane;
        if (s < Slen) {
            const float* qp = &sq[w*304];
            const float* sp = &ssrc[lane*SB];
            float a0 = 0.f, a1 = 0.f, a2 = 0.f, a3 = 0.f;
            #pragma unroll 5
            for (int h4 = 0; h4 < Hd; h4 += 4) {
                float4 qv = *(const float4*)(qp + h4);
                float4 sv = *(const float4*)(sp + h4);
                a0 += qv.x*sv.x; a1 += qv.y*sv.y;
                a2 += qv.z*sv.z; a3 += qv.w*sv.w;
            }
            int mk = useu8 ? (int)m8[b*Slen + s] : m32[b*Slen + s];
            ssc[w*400 + s] = mk ? ((a0+a1) + (a2+a3)) : -1e9f;
        }
    }
    __syncthreads();

    // ---- softmax (warp-local) + write attn_out ----
    {
        float mv = -3.4e38f;
        for (int s = lane; s < Slen; s += 32) mv = fmaxf(mv, ssc[w*400 + s]);
        #pragma unroll
        for (int o = 16; o; o >>= 1) mv = fmaxf(mv, __shfl_xor_sync(0xffffffffu, mv, o));
        float sv = 0.f;
        for (int s = lane; s < Slen; s += 32) {
            float e = __expf(ssc[w*400 + s] - mv);
            ssc[w*400 + s] = e;
            sv += e;
        }
        #pragma unroll
        for (int o = 16; o; o >>= 1) sv += __shfl_xor_sync(0xffffffffu, sv, o);
        float inv = 1.f / sv;
        for (int s = lane; s < Slen; s += 32) {
            float pn = ssc[w*400 + s] * inv;
            ssc[w*400 + s] = pn;
            attn_out[(size_t)row*Slen + s] = pn;
        }
    }
    __syncwarp();

    // ---- contexts ----
    float4 c0 = make_float4(0.f,0.f,0.f,0.f);
    float4 c1 = make_float4(0.f,0.f,0.f,0.f);
    float4 c2 = make_float4(0.f,0.f,0.f,0.f);
    const int h2 = 256 + lane*4;
    for (int s0 = 0; s0 < Slen; s0 += 32) {
        __syncthreads();
        for (int i = tid; i < 32*75; i += 256) {
            int s = i / 75, q4 = (i - s*75)*4;
            if (s0 + s < Slen)
                *(float4*)&ssrc[s*SB + q4] =
                    *(const float4*)(src + ((size_t)b*Slen + s0 + s)*Hd + q4);
        }
        __syncthreads();
        int smax = Slen - s0; if (smax > 32) smax = 32;
        for (int ss = 0; ss < smax; ss++) {
            float pp = ssc[w*400 + s0 + ss];
            const float* sp = &ssrc[ss*SB];
            float4 v0 = *(const float4*)(sp + lane*4);
            float4 v1 = *(const float4*)(sp + 128 + lane*4);
            c0.x += pp*v0.x; c0.y += pp*v0.y; c0.z += pp*v0.z; c0.w += pp*v0.w;
            c1.x += pp*v1.x; c1.y += pp*v1.y; c1.z += pp*v1.z; c1.w += pp*v1.w;
            if (h2 < Hd) {
                float4 v2 = *(const float4*)(sp + h2);
                c2.x += pp*v2.x; c2.y += pp*v2.y; c2.z += pp*v2.z; c2.w += pp*v2.w;
            }
        }
    }
    *(float4*)&g_cat[row*CATW + lane*4]       = c0;
    *(float4*)&g_cat[row*CATW + 128 + lane*4] = c1;
    if (h2 < Hd) *(float4*)&g_cat[row*CATW + h2] = c2;
}

// ---------------------------------------------------------------------------
// p_gen (unchanged)
// ---------------------------------------------------------------------------
__global__ void pgen_kernel(const float* __restrict__ pW,
                            const float* __restrict__ pb) {
    int wg = blockIdx.x*(blockDim.x >> 5) + (threadIdx.x >> 5);
    if (wg >= ROWS) return;
    int lane = threadIdx.x & 31;
    const float* crow = g_cat + wg*CATW;
    float a0 = 0.f, a1 = 0.f;
    for (int k = lane; k < CATW; k += 32) {
        float v = crow[k];
        a0 += v*pW[k];
        a1 += v*pW[CATW + k];
    }
    #pragma unroll
    for (int o = 16; o; o >>= 1) {
        a0 += __shfl_xor_sync(0xffffffffu, a0, o);
        a1 += __shfl_xor_sync(0xffffffffu, a1, o);
    }
    if (lane == 0) {
        float l0 = a0 + pb[0], l1 = a1 + pb[1];
        float m = fmaxf(l0, l1);
        float e0 = __expf(l0 - m), e1 = __expf(l1 - m);
        float inv = 1.f/(e0 + e1);
        g_pgen[wg*2+0] = e0*inv;
        g_pgen[wg*2+1] = e1*inv;
    }
}

// ---------------------------------------------------------------------------
// Merged final scale + copy scatter — float4-vectorized main pass.
// VO=50020 and Vocab=50000 are 4-divisible; row bases 16B-aligned.
// ---------------------------------------------------------------------------
__global__ void __launch_bounds__(256) scale_scatter_kernel(
        float* __restrict__ out, const int* __restrict__ src_oov,
        const float* __restrict__ attn) {
    int row = blockIdx.x;
    int b = row / Tlen;
    float scale = g_pgen[row*2] / g_rowsum[row];
    const float* lrow = g_logits + (size_t)row*Vocab;
    float* orow = out + (size_t)row*VO;
    for (int v4 = threadIdx.x; v4 < VO/4; v4 += 256) {
        float4 o;
        if (v4 < Vocab/4) {
            float4 l = *(const float4*)&lrow[v4*4];
            o = make_float4(scale*l.x, scale*l.y, scale*l.z, scale*l.w);
        } else {
            o = make_float4(0.f, 0.f, 0.f, 0.f);
        }
        *(float4*)&orow[v4*4] = o;
    }
    __syncthreads();
    float p1 = g_pgen[row*2+1];
    for (int s = threadIdx.x; s < Slen; s += 256) {
        float a = attn[(size_t)row*Slen + s] * p1;
        int col = src_oov[b*Slen + s];
        atomicAdd(&orow[col], a);
    }
}

// ---------------------------------------------------------------------------
// Host launcher
// ---------------------------------------------------------------------------
extern "C" void kernel_launch(void* const* d_in, const int* in_sizes, int n_in,
                              void* d_out, int out_size) {
    int idx = 0;
    const int*   tokens  = (const int*)  d_in[idx++];
    const float* src     = (const float*)d_in[idx++];
    const void*  mask    =               d_in[idx++];
    const float* hidden0 = (const float*)d_in[idx++];
    const int*   src_oov = (const int*)  d_in[idx++];
    if (idx < n_in && in_sizes[idx] == 1) idx++;   // max_num_oov scalar
    const float* embed   = (const float*)d_in[idx++];
    const float* W_ih    = (const float*)d_in[idx++];
    const float* W_hh    = (const float*)d_in[idx++];
    const float* b_ih    = (const float*)d_in[idx++];
    const float* b_hh    = (const float*)d_in[idx++];
    const float* attn_W  = (const float*)d_in[idx++];
    const float* attn_b  = (const float*)d_in[idx++];
    const float* fc_W    = (const float*)d_in[idx++];
    const float* fc_b    = (const float*)d_in[idx++];
    const float* out_W   = (const float*)d_in[idx++];
    const float* out_b   = (const float*)d_in[idx++];
    const float* pgen_W  = (const float*)d_in[idx++];
    const float* pgen_b  = (const float*)d_in[idx++];

    float* out = (float*)d_out;
    float* attn_out;
    if (out_size >= (int)((size_t)ROWS*VO + (size_t)ROWS*Slen)) {
        attn_out = out + (size_t)ROWS*VO;
    } else {
        void* p = nullptr;
        cudaGetSymbolAddress(&p, g_attn_fallback);
        attn_out = (float*)p;
    }

    cudaFuncSetAttribute(gru_persistent_kernel,
                         cudaFuncAttributeMaxDynamicSharedMemorySize, SMEM_BYTES);
    cudaFuncSetAttribute(attn_kernel,
                         cudaFuncAttributeMaxDynamicSharedMemorySize, ATT_BYTES);

    detect_mask_kernel<<<1,1>>>((const unsigned char*)mask);
    init_hall_kernel<<<(Ld*Bsz*Hd+255)/256,256>>>(hidden0);
    embed_kernel<<<(ROWS*Ed+255)/256,256>>>(tokens, embed);

    // B-split conversion is GRU-independent; issue before the GRU chain.
    convertB_kernel<<<(BROWS*(KP/2)+255)/256,256>>>(out_W);

    gru_persistent_kernel<<<NBLK, NTHR, SMEM_BYTES>>>(W_ih, W_hh, b_ih, b_hh);

    gemm_kernel<<<dim3(5,8),256>>>(MODE_Q, attn_W, attn_b, Hd, Hd, CATW);
    attn_kernel<<<64,256, ATT_BYTES>>>(src, mask, attn_out);
    gemm_kernel<<<dim3(5,8),256>>>(MODE_FEAT, fc_W, fc_b, Hd, 2*Hd, CATW);
    pgen_kernel<<<64,256>>>(pgen_W, pgen_b);

    convertA_kernel<<<(ROWS*(KP/2)+255)/256,256>>>();
    out_gemm_mma_kernel<<<dim3(4,391),256>>>(out_b);
    scale_scatter_kernel<<<ROWS,256>>>(out, src_oov, attn_out);
}